// round 13
// baseline (speedup 1.0000x reference)
#include <cuda_runtime.h>

#define NB 32
#define NC 64
#define NS 64
#define NE 6      // distinct experts (PERM folds 8 gates onto 6)
#define GRID 592  // exactly 4 blocks/SM on 148 SMs — all co-resident

// Scratch (device globals)
__device__ float g_c  [4 * 16 * 64 * 32];          // [band][xy][i(chan)][b]
__device__ float g_Wt2[4 * 16 * NE * 64 * 64];     // [band][xy][e][i][o]  (6.3MB)
__device__ float g_S  [32 * 16 * 24 * 64];         // [b][xy][e*4+band][o]  (3MB)
__device__ float g_z  [NB * NC * 64];              // [b][c][XY] pre-scaled 1/16
__device__ float g_Wsum[NB];
__device__ unsigned g_count = 0;
__device__ unsigned g_gen = 0;

// Sense-reversing grid barrier. Safe because all GRID blocks are co-resident.
__device__ __forceinline__ void gridbar() {
    __syncthreads();
    if (threadIdx.x == 0) {
        unsigned gen = *(volatile unsigned*)&g_gen;   // read BEFORE arrival
        __threadfence();
        unsigned arr = atomicAdd(&g_count, 1);
        if (arr == GRID - 1) {
            g_count = 0;
            __threadfence();
            atomicAdd(&g_gen, 1);                     // release
        } else {
            while (*(volatile unsigned*)&g_gen == gen) __nanosleep(64);
        }
        __threadfence();
    }
    __syncthreads();
}

__global__ void __launch_bounds__(256, 4)
kFused(const float* __restrict__ x,
       const float* __restrict__ WL, const float* __restrict__ WH,
       const float* __restrict__ lam,
       float* __restrict__ out) {
    __shared__ float sh[2048];        // 8KB, reused across phases
    int blk = blockIdx.x;
    int t = threadIdx.x;              // 0..255

    // ================= Phase A: transpose W + x block-sums =================
    for (int u = blk; u < 896; u += GRID) {
        if (u < 384) {
            if (u == 0 && t < 32) {
                const float* lp = lam + t * 8;
                g_Wsum[t] = lp[0]+lp[1]+lp[2]+lp[3]+lp[4]+lp[5]+lp[6]+lp[7];
            }
            int be = u >> 4;          // band*6+e
            int rr = u & 15;
            int band = be / NE, e = be % NE;
            const float* src;
            if (band == 0) src = WL + (size_t)e * 65536;
            else           src = WH + (size_t)(e * 3 + (band - 1)) * 65536;
            int io = t + 256 * rr;    // 0..4095
            const float* sp = src + (size_t)io * 16;
            float4 q0 = *(const float4*)(sp);
            float4 q1 = *(const float4*)(sp + 4);
            float4 q2 = *(const float4*)(sp + 8);
            float4 q3 = *(const float4*)(sp + 12);
            float v[16] = {q0.x,q0.y,q0.z,q0.w, q1.x,q1.y,q1.z,q1.w,
                           q2.x,q2.y,q2.z,q2.w, q3.x,q3.y,q3.z,q3.w};
            float* dbase = g_Wt2 + (size_t)band * 16 * 24576 + (size_t)e * 4096 + io;
#pragma unroll
            for (int xy = 0; xy < 16; xy++)
                dbase[(size_t)xy * 24576] = v[xy];
        } else {
            float (*ll3)[64] = (float(*)[64])sh;      // [4][64]
            int sub = t >> 6, tt = t & 63;
            int bc = ((u - 384) << 2) + sub;          // 0..2047
            int i = tt >> 3, j = tt & 7;
            const float* xp = x + (size_t)bc * NS * NS + (size_t)i * 8 * NS + j * 8;
            float s = 0.f;
#pragma unroll
            for (int r = 0; r < 8; r++) {
                float4 a = *(const float4*)(xp + r * NS);
                float4 b = *(const float4*)(xp + r * NS + 4);
                s += a.x + a.y + a.z + a.w + b.x + b.y + b.z + b.w;
            }
            ll3[sub][tt] = s * 0.125f;
            __syncthreads();
            if (tt < 16) {
                int xy = tt;
                int xx = xy >> 2, yy = xy & 3;
                float a = ll3[sub][(2 * xx) * 8 + 2 * yy];
                float b = ll3[sub][(2 * xx) * 8 + 2 * yy + 1];
                float c = ll3[sub][(2 * xx + 1) * 8 + 2 * yy];
                float d = ll3[sub][(2 * xx + 1) * 8 + 2 * yy + 1];
                int bb = bc >> 6, ch = bc & 63;
                float v[4];
                v[0] = (a + b + c + d) * 0.5f;
                v[1] = (a + b - c - d) * 0.5f;
                v[2] = (a - b + c - d) * 0.5f;
                v[3] = (a - b - c + d) * 0.5f;
#pragma unroll
                for (int band = 0; band < 4; band++)
                    g_c[((band * 16 + xy) * 64 + ch) * 32 + bb] = v[band];
            }
            __syncthreads();          // before ll3 reuse / next unit
        }
    }

    gridbar();

    // ================= Phase B: gated GEMM (blocks 0..383) =================
    if (blk < 384) {
        float* wcsh = sh;             // [i][b] 64x32 = 8KB
        int e = blk % NE;
        int bx = blk / NE;
        int xy = bx & 15;
        int band = bx >> 4;
        int bl = t & 31;

        const float* lp = lam + bl * 8;
        float we;
        if      (e == 0) we = lp[0];
        else if (e == 1) we = lp[1];
        else if (e == 2) we = lp[2];
        else if (e == 3) we = lp[3];
        else if (e == 4) we = lp[4] + lp[6];
        else             we = lp[5] + lp[7];

        const float* cbase = g_c + (size_t)(band * 16 + xy) * 2048;   // [i][b]
#pragma unroll
        for (int r = 0; r < 8; r++) {
            int j = t + 256 * r;
            wcsh[j] = cbase[j] * we;
        }
        __syncthreads();

        int b0 = (t >> 4) * 2;        // 0..30
        int o0 = (t & 15) * 4;        // 0..60
        const float* wbase = g_Wt2 + ((size_t)(band * 16 + xy) * NE + e) * 4096 + o0;
        float a0x = 0.f, a0y = 0.f, a0z = 0.f, a0w = 0.f;
        float a1x = 0.f, a1y = 0.f, a1z = 0.f, a1w = 0.f;
#pragma unroll 8
        for (int k = 0; k < 64; k++) {
            float2 c2 = *(const float2*)(wcsh + k * 32 + b0);
            float4 w4 = *(const float4*)(wbase + k * 64);
            a0x += c2.x * w4.x; a0y += c2.x * w4.y; a0z += c2.x * w4.z; a0w += c2.x * w4.w;
            a1x += c2.y * w4.x; a1y += c2.y * w4.y; a1z += c2.y * w4.z; a1w += c2.y * w4.w;
        }

        if (e == 0) {
            float Wt0 = g_Wsum[b0], Wt1 = g_Wsum[b0 + 1];
            a0x -= Wt0 * cbase[(o0    ) * 32 + b0];
            a0y -= Wt0 * cbase[(o0 + 1) * 32 + b0];
            a0z -= Wt0 * cbase[(o0 + 2) * 32 + b0];
            a0w -= Wt0 * cbase[(o0 + 3) * 32 + b0];
            a1x -= Wt1 * cbase[(o0    ) * 32 + b0 + 1];
            a1y -= Wt1 * cbase[(o0 + 1) * 32 + b0 + 1];
            a1z -= Wt1 * cbase[(o0 + 2) * 32 + b0 + 1];
            a1w -= Wt1 * cbase[(o0 + 3) * 32 + b0 + 1];
        }

        int eb = e * 4 + band;
        float* Sp = g_S + (((size_t)(b0 * 16 + xy)) * 24 + eb) * 64 + o0;
        *(float4*)Sp            = make_float4(a0x, a0y, a0z, a0w);
        *(float4*)(Sp + 24576)  = make_float4(a1x, a1y, a1z, a1w);   // b0+1
    }

    gridbar();

    // ===== Phase Bz: expert-sum + IDWT -> g_z[b][c][XY]  (c-fastest, R6 kR) =====
    {
        int tid = blk * 256 + t;      // 0..151551; need 131072
        if (tid < 131072) {
            int c = tid & 63;
            int XY = (tid >> 6) & 63;
            int b = tid >> 12;
            int X = XY >> 3, Y = XY & 7;
            int xy = ((X >> 1) << 2) + (Y >> 1);
            float s1 = (X & 1) ? -1.f : 1.f;
            float s2 = (Y & 1) ? -1.f : 1.f;
            float s3 = s1 * s2;
            const float* p = g_S + ((size_t)(b * 16 + xy) * 24) * 64 + c;
            float z = 0.f;
#pragma unroll
            for (int e = 0; e < NE; e++) {
                float S0 = p[e * 256];
                float S1 = p[e * 256 + 64];
                float S2 = p[e * 256 + 128];
                float S3 = p[e * 256 + 192];
                z += S0 + s1 * S1 + s2 * S2 + s3 * S3;
            }
            g_z[((size_t)b << 12) + (c << 6) + XY] = z * 0.0625f;
        }
    }

    gridbar();

    // ===== Phase C: flat sync-free AXPY: out = Wsum[b]*x + z  =====
    {
        int gtid = blk * 256 + t;     // 0..151551
        for (int i = gtid; i < 2097152; i += GRID * 256) {
            int e0 = i << 2;
            int bc = e0 >> 12;        // (b<<6)|c
            int h = (e0 >> 6) & 63;
            int w0 = e0 & 63;
            float W = g_Wsum[bc >> 6];
            float zv = __ldg(g_z + ((size_t)bc << 6) + ((h >> 3) << 3) + (w0 >> 3));
            float4 xv = *(const float4*)(x + e0);
            float4 ov;
            ov.x = fmaf(W, xv.x, zv);
            ov.y = fmaf(W, xv.y, zv);
            ov.z = fmaf(W, xv.z, zv);
            ov.w = fmaf(W, xv.w, zv);
            *(float4*)(out + e0) = ov;
        }
    }
}

// ---------------------------------------------------------------------------
extern "C" void kernel_launch(void* const* d_in, const int* in_sizes, int n_in,
                              void* d_out, int out_size) {
    const float* x   = (const float*)d_in[0];  // [32,64,64,64]
    const float* lam = (const float*)d_in[1];  // [32,1,8,1]
    const float* WL  = (const float*)d_in[2];  // [8,64,64,4,4]
    const float* WH  = (const float*)d_in[3];  // [8,3,64,64,4,4]
    float* out = (float*)d_out;

    kFused<<<GRID, 256>>>(x, WL, WH, lam, out);
    (void)in_sizes; (void)n_in; (void)out_size;
}

// round 14
// speedup vs baseline: 1.0691x; 1.0691x over previous
#include <cuda_runtime.h>

#define NB 32
#define NC 64
#define NS 64
#define NE 6      // distinct experts (PERM folds 8 gates onto 6)
#define GRID 512  // <= 592 (4/SM cap) => all co-resident; 2048/512 = 4 images exactly

// Scratch (device globals)
__device__ float g_c  [4 * 16 * 64 * 32];          // [band][xy][i(chan)][b]
__device__ float g_Wt2[4 * 16 * NE * 64 * 64];     // [band][xy][e][i][o]  (6.3MB)
__device__ float g_S  [32 * 16 * 24 * 64];         // [b][xy][e*4+band][o]  (3MB)
__device__ float g_Wsum[NB];
__device__ unsigned g_count = 0;
__device__ unsigned g_gen = 0;

// Sense-reversing grid barrier. Safe because all GRID blocks are co-resident.
__device__ __forceinline__ void gridbar() {
    __syncthreads();
    if (threadIdx.x == 0) {
        unsigned gen = *(volatile unsigned*)&g_gen;   // read BEFORE arrival
        __threadfence();
        unsigned arr = atomicAdd(&g_count, 1);
        if (arr == GRID - 1) {
            g_count = 0;
            __threadfence();
            atomicAdd(&g_gen, 1);                     // release
        } else {
            while (*(volatile unsigned*)&g_gen == gen) __nanosleep(64);
        }
        __threadfence();
    }
    __syncthreads();
}

__global__ void __launch_bounds__(256, 4)
kFused(const float* __restrict__ x,
       const float* __restrict__ WL, const float* __restrict__ WH,
       const float* __restrict__ lam,
       float* __restrict__ out) {
    __shared__ float sh[2048];        // 8KB, reused across phases
    int blk = blockIdx.x;
    int t = threadIdx.x;              // 0..255

    // ================= Phase A: transpose W + x block-sums =================
    for (int u = blk; u < 896; u += GRID) {
        if (u < 384) {
            if (u == 0 && t < 32) {
                const float* lp = lam + t * 8;
                g_Wsum[t] = lp[0]+lp[1]+lp[2]+lp[3]+lp[4]+lp[5]+lp[6]+lp[7];
            }
            int be = u >> 4;          // band*6+e
            int rr = u & 15;
            int band = be / NE, e = be % NE;
            const float* src;
            if (band == 0) src = WL + (size_t)e * 65536;
            else           src = WH + (size_t)(e * 3 + (band - 1)) * 65536;
            int io = t + 256 * rr;    // 0..4095
            const float* sp = src + (size_t)io * 16;
            float4 q0 = *(const float4*)(sp);
            float4 q1 = *(const float4*)(sp + 4);
            float4 q2 = *(const float4*)(sp + 8);
            float4 q3 = *(const float4*)(sp + 12);
            float v[16] = {q0.x,q0.y,q0.z,q0.w, q1.x,q1.y,q1.z,q1.w,
                           q2.x,q2.y,q2.z,q2.w, q3.x,q3.y,q3.z,q3.w};
            float* dbase = g_Wt2 + (size_t)band * 16 * 24576 + (size_t)e * 4096 + io;
#pragma unroll
            for (int xy = 0; xy < 16; xy++)
                dbase[(size_t)xy * 24576] = v[xy];
        } else {
            float (*ll3)[64] = (float(*)[64])sh;      // [4][64]
            int sub = t >> 6, tt = t & 63;
            int bc = ((u - 384) << 2) + sub;          // 0..2047
            int i = tt >> 3, j = tt & 7;
            const float* xp = x + (size_t)bc * NS * NS + (size_t)i * 8 * NS + j * 8;
            float s = 0.f;
#pragma unroll
            for (int r = 0; r < 8; r++) {
                float4 a = *(const float4*)(xp + r * NS);
                float4 b = *(const float4*)(xp + r * NS + 4);
                s += a.x + a.y + a.z + a.w + b.x + b.y + b.z + b.w;
            }
            ll3[sub][tt] = s * 0.125f;
            __syncthreads();
            if (tt < 16) {
                int xy = tt;
                int xx = xy >> 2, yy = xy & 3;
                float a = ll3[sub][(2 * xx) * 8 + 2 * yy];
                float b = ll3[sub][(2 * xx) * 8 + 2 * yy + 1];
                float c = ll3[sub][(2 * xx + 1) * 8 + 2 * yy];
                float d = ll3[sub][(2 * xx + 1) * 8 + 2 * yy + 1];
                int bb = bc >> 6, ch = bc & 63;
                float v[4];
                v[0] = (a + b + c + d) * 0.5f;
                v[1] = (a + b - c - d) * 0.5f;
                v[2] = (a - b + c - d) * 0.5f;
                v[3] = (a - b - c + d) * 0.5f;
#pragma unroll
                for (int band = 0; band < 4; band++)
                    g_c[((band * 16 + xy) * 64 + ch) * 32 + bb] = v[band];
            }
            __syncthreads();          // before ll3 reuse / next unit
        }
    }

    gridbar();

    // ================= Phase B: gated GEMM (blocks 0..383) =================
    if (blk < 384) {
        float* wcsh = sh;             // [i][b] 64x32 = 8KB
        int e = blk % NE;
        int bx = blk / NE;
        int xy = bx & 15;
        int band = bx >> 4;
        int bl = t & 31;

        const float* lp = lam + bl * 8;
        float we;
        if      (e == 0) we = lp[0];
        else if (e == 1) we = lp[1];
        else if (e == 2) we = lp[2];
        else if (e == 3) we = lp[3];
        else if (e == 4) we = lp[4] + lp[6];
        else             we = lp[5] + lp[7];

        const float* cbase = g_c + (size_t)(band * 16 + xy) * 2048;   // [i][b]
#pragma unroll
        for (int r = 0; r < 8; r++) {
            int j = t + 256 * r;
            wcsh[j] = cbase[j] * we;
        }
        __syncthreads();

        int b0 = (t >> 4) * 2;        // 0..30
        int o0 = (t & 15) * 4;        // 0..60
        const float* wbase = g_Wt2 + ((size_t)(band * 16 + xy) * NE + e) * 4096 + o0;
        float a0x = 0.f, a0y = 0.f, a0z = 0.f, a0w = 0.f;
        float a1x = 0.f, a1y = 0.f, a1z = 0.f, a1w = 0.f;
#pragma unroll 8
        for (int k = 0; k < 64; k++) {
            float2 c2 = *(const float2*)(wcsh + k * 32 + b0);
            float4 w4 = *(const float4*)(wbase + k * 64);
            a0x += c2.x * w4.x; a0y += c2.x * w4.y; a0z += c2.x * w4.z; a0w += c2.x * w4.w;
            a1x += c2.y * w4.x; a1y += c2.y * w4.y; a1z += c2.y * w4.z; a1w += c2.y * w4.w;
        }

        if (e == 0) {
            float Wt0 = g_Wsum[b0], Wt1 = g_Wsum[b0 + 1];
            a0x -= Wt0 * cbase[(o0    ) * 32 + b0];
            a0y -= Wt0 * cbase[(o0 + 1) * 32 + b0];
            a0z -= Wt0 * cbase[(o0 + 2) * 32 + b0];
            a0w -= Wt0 * cbase[(o0 + 3) * 32 + b0];
            a1x -= Wt1 * cbase[(o0    ) * 32 + b0 + 1];
            a1y -= Wt1 * cbase[(o0 + 1) * 32 + b0 + 1];
            a1z -= Wt1 * cbase[(o0 + 2) * 32 + b0 + 1];
            a1w -= Wt1 * cbase[(o0 + 3) * 32 + b0 + 1];
        }

        int eb = e * 4 + band;
        float* Sp = g_S + (((size_t)(b0 * 16 + xy)) * 24 + eb) * 64 + o0;
        *(float4*)Sp            = make_float4(a0x, a0y, a0z, a0w);
        *(float4*)(Sp + 24576)  = make_float4(a1x, a1y, a1z, a1w);   // b0+1
    }

    gridbar();

    // ===== Phase C: expert-sum + IDWT + AXPY, exactly 4 contiguous images =====
#pragma unroll
    for (int ii = 0; ii < 4; ii++) {
        int img = (blk << 2) + ii;    // 0..2047, contiguous per block
        int b = img >> 6, c = img & 63;
        if (t < 64) {
            int X = t >> 3, Y = t & 7;
            int xy = ((X >> 1) << 2) + (Y >> 1);
            float s1 = (X & 1) ? -1.f : 1.f;
            float s2 = (Y & 1) ? -1.f : 1.f;
            float s3 = s1 * s2;
            const float* p = g_S + ((size_t)(b * 16 + xy) * 24) * 64 + c;
            float z = 0.f;
#pragma unroll
            for (int e = 0; e < NE; e++) {
                float S0 = p[e * 256];
                float S1 = p[e * 256 + 64];
                float S2 = p[e * 256 + 128];
                float S3 = p[e * 256 + 192];
                z += S0 + s1 * S1 + s2 * S2 + s3 * S3;
            }
            sh[(ii << 6) + t] = z * 0.0625f;   // separate 64-float slot per image
        }
        float W = g_Wsum[b];
        __syncthreads();

        const float* xp = x + (size_t)img * 4096;
        float* op = out + (size_t)img * 4096;
#pragma unroll
        for (int k = 0; k < 4; k++) {
            int idx = (t << 2) + (k << 10);          // warp-contiguous within slot
            float zv = sh[(ii << 6) + ((idx >> 9) << 3) + ((idx & 63) >> 3)];
            float4 xv = *(const float4*)(xp + idx);
            float4 ov;
            ov.x = fmaf(W, xv.x, zv);
            ov.y = fmaf(W, xv.y, zv);
            ov.z = fmaf(W, xv.z, zv);
            ov.w = fmaf(W, xv.w, zv);
            *(float4*)(op + idx) = ov;
        }
        // no trailing sync needed: each image uses its own sh slot
    }
}

// ---------------------------------------------------------------------------
extern "C" void kernel_launch(void* const* d_in, const int* in_sizes, int n_in,
                              void* d_out, int out_size) {
    const float* x   = (const float*)d_in[0];  // [32,64,64,64]
    const float* lam = (const float*)d_in[1];  // [32,1,8,1]
    const float* WL  = (const float*)d_in[2];  // [8,64,64,4,4]
    const float* WH  = (const float*)d_in[3];  // [8,3,64,64,4,4]
    float* out = (float*)d_out;

    kFused<<<GRID, 256>>>(x, WL, WH, lam, out);
    (void)in_sizes; (void)n_in; (void)out_size;
}